// round 1
// baseline (speedup 1.0000x reference)
#include <cuda_runtime.h>

// VoxelBracketPredictor_v2: fused segment-mean-pool + coarse MLP + routed refinement head.
// One CTA per sample (B=4096 blocks, 256 threads). Deterministic (no atomics).
//
// Inputs (metadata order):
//  0 feat [N,96] f32          1 segment_ids [N] i32 (sorted)   2 class_ids [B] i32
//  3 cW1 [96,256]  4 cb1[256] 5 cg1[256] 6 cbe1[256]
//  7 cW2 [256,128] 8 cb2[128] 9 cg2[128] 10 cbe2[128]
// 11 cW3 [128,3]  12 cb3[3]
// 13 rW1 [4,96,128] 14 rb1[4,128] 15 rg1[4,128] 16 rbe1[4,128]
// 17 rW2 [4,128,64] 18 rb2[4,64]  19 rg2[4,64]  20 rbe2[4,64]
// 21 rW3 [4,64,3]   22 rb3[4,3]
// out [B,3] f32

#define EPS 1e-5f

// Block-wide sum over 256 threads (8 warps). Leading sync protects `red` reuse.
__device__ __forceinline__ float blockSum(float v, float* red) {
    __syncthreads();
#pragma unroll
    for (int o = 16; o; o >>= 1) v += __shfl_xor_sync(0xffffffffu, v, o);
    if ((threadIdx.x & 31) == 0) red[threadIdx.x >> 5] = v;
    __syncthreads();
    float s = 0.f;
#pragma unroll
    for (int i = 0; i < 8; i++) s += red[i];
    return s;
}

__device__ __forceinline__ int lowerBound(const int* __restrict__ a, int n, int v) {
    int lo = 0, hi = n;
    while (lo < hi) {
        int mid = (lo + hi) >> 1;
        if (a[mid] < v) lo = mid + 1; else hi = mid;
    }
    return lo;
}

__global__ __launch_bounds__(256) void vbp_fused_kernel(
    const float* __restrict__ feat, const int* __restrict__ seg,
    const int* __restrict__ cls,
    const float* __restrict__ cW1, const float* __restrict__ cb1,
    const float* __restrict__ cg1, const float* __restrict__ cbe1,
    const float* __restrict__ cW2, const float* __restrict__ cb2,
    const float* __restrict__ cg2, const float* __restrict__ cbe2,
    const float* __restrict__ cW3, const float* __restrict__ cb3,
    const float* __restrict__ rW1, const float* __restrict__ rb1,
    const float* __restrict__ rg1, const float* __restrict__ rbe1,
    const float* __restrict__ rW2, const float* __restrict__ rb2,
    const float* __restrict__ rg2, const float* __restrict__ rbe2,
    const float* __restrict__ rW3, const float* __restrict__ rb3,
    float* __restrict__ out, int N)
{
    __shared__ float part[8][96];
    __shared__ float sp[96];     // pooled features
    __shared__ float s1[256];    // h1 / r1
    __shared__ float s2[128];    // h2 / r2
    __shared__ float red[8];

    const int b    = blockIdx.x;
    const int tid  = threadIdx.x;
    const int lane = tid & 31;
    const int w    = tid >> 5;

    // ---- segment boundaries via binary search on sorted ids ----
    const int start = lowerBound(seg, N, b);
    const int end   = lowerBound(seg, N, b + 1);

    // ---- mean pool: warp-strided rows, lane covers 3 channels ----
    float a0 = 0.f, a1 = 0.f, a2 = 0.f;
    for (int r = start + w; r < end; r += 8) {
        const float* f = feat + (long)r * 96;
        a0 += f[lane];
        a1 += f[lane + 32];
        a2 += f[lane + 64];
    }
    part[w][lane]      = a0;
    part[w][lane + 32] = a1;
    part[w][lane + 64] = a2;
    __syncthreads();
    if (tid < 96) {
        float s = 0.f;
#pragma unroll
        for (int i = 0; i < 8; i++) s += part[i][tid];
        sp[tid] = s / fmaxf((float)(end - start), 1.f);
    }
    __syncthreads();

    // ---- coarse layer 1: 96 -> 256, LN, ReLU ----
    float x = cb1[tid];
#pragma unroll 8
    for (int c = 0; c < 96; c++) x = fmaf(sp[c], cW1[c * 256 + tid], x);
    float mean = blockSum(x, red) * (1.f / 256.f);
    float d = x - mean;
    float var = blockSum(d * d, red) * (1.f / 256.f);
    s1[tid] = fmaxf(fmaf(d * rsqrtf(var + EPS), cg1[tid], cbe1[tid]), 0.f);
    __syncthreads();

    // ---- coarse layer 2: 256 -> 128, LN, ReLU ----
    const bool act2 = tid < 128;
    float y = 0.f;
    if (act2) {
        y = cb2[tid];
#pragma unroll 8
        for (int c = 0; c < 256; c++) y = fmaf(s1[c], cW2[c * 128 + tid], y);
    }
    mean = blockSum(act2 ? y : 0.f, red) * (1.f / 128.f);
    d = act2 ? (y - mean) : 0.f;
    var = blockSum(d * d, red) * (1.f / 128.f);
    if (act2) s2[tid] = fmaxf(fmaf(d * rsqrtf(var + EPS), cg2[tid], cbe2[tid]), 0.f);
    __syncthreads();

    // ---- coarse output: 128 -> 3 (kept in registers of threads 0..2) ----
    float coarse = 0.f;
    if (tid < 3) {
        coarse = cb3[tid];
#pragma unroll 8
        for (int c = 0; c < 128; c++) coarse = fmaf(s2[c], cW3[c * 3 + tid], coarse);
    }

    // ---- refinement: only the routed head k ----
    const int k = cls[b];

    // r1: 96 -> 128, LN, ReLU
    float z = 0.f;
    if (act2) {
        z = rb1[k * 128 + tid];
        const float* Wk = rW1 + (long)k * 96 * 128;
#pragma unroll 8
        for (int c = 0; c < 96; c++) z = fmaf(sp[c], Wk[c * 128 + tid], z);
    }
    mean = blockSum(act2 ? z : 0.f, red) * (1.f / 128.f);
    d = act2 ? (z - mean) : 0.f;
    var = blockSum(d * d, red) * (1.f / 128.f);
    if (act2) s1[tid] = fmaxf(fmaf(d * rsqrtf(var + EPS), rg1[k * 128 + tid], rbe1[k * 128 + tid]), 0.f);
    __syncthreads();

    // r2: 128 -> 64, LN, ReLU
    const bool act3 = tid < 64;
    float u = 0.f;
    if (act3) {
        u = rb2[k * 64 + tid];
        const float* Wk = rW2 + (long)k * 128 * 64;
#pragma unroll 8
        for (int c = 0; c < 128; c++) u = fmaf(s1[c], Wk[c * 64 + tid], u);
    }
    mean = blockSum(act3 ? u : 0.f, red) * (1.f / 64.f);
    d = act3 ? (u - mean) : 0.f;
    var = blockSum(d * d, red) * (1.f / 64.f);
    if (act3) s2[tid] = fmaxf(fmaf(d * rsqrtf(var + EPS), rg2[k * 64 + tid], rbe2[k * 64 + tid]), 0.f);
    __syncthreads();

    // r3: 64 -> 3, add coarse, write out
    if (tid < 3) {
        float off = rb3[k * 3 + tid];
        const float* Wk = rW3 + (long)k * 64 * 3;
#pragma unroll 8
        for (int c = 0; c < 64; c++) off = fmaf(s2[c], Wk[c * 3 + tid], off);
        out[b * 3 + tid] = coarse + off;
    }
}

extern "C" void kernel_launch(void* const* d_in, const int* in_sizes, int n_in,
                              void* d_out, int out_size) {
    const float* feat = (const float*)d_in[0];
    const int*   seg  = (const int*)d_in[1];
    const int*   cls  = (const int*)d_in[2];
    const int N = in_sizes[1];
    const int B = in_sizes[2];

    vbp_fused_kernel<<<B, 256>>>(
        feat, seg, cls,
        (const float*)d_in[3],  (const float*)d_in[4],  (const float*)d_in[5],  (const float*)d_in[6],
        (const float*)d_in[7],  (const float*)d_in[8],  (const float*)d_in[9],  (const float*)d_in[10],
        (const float*)d_in[11], (const float*)d_in[12],
        (const float*)d_in[13], (const float*)d_in[14], (const float*)d_in[15], (const float*)d_in[16],
        (const float*)d_in[17], (const float*)d_in[18], (const float*)d_in[19], (const float*)d_in[20],
        (const float*)d_in[21], (const float*)d_in[22],
        (float*)d_out, N);
}

// round 2
// speedup vs baseline: 1.2574x; 1.2574x over previous
#include <cuda_runtime.h>

// VoxelBracketPredictor_v2 — 3-kernel pipeline:
//  k0: segment boundaries via linear scan of sorted segment_ids
//  k1: mean-pool (warp per sample, float4, fully coalesced)
//  k2: MLP with 16-sample batching per CTA (weights reused x16 in registers)
//
// Inputs (metadata order):
//  0 feat[N,96] f32  1 seg[N] i32 sorted  2 cls[B] i32
//  3 cW1[96,256] 4 cb1 5 cg1 6 cbe1   7 cW2[256,128] 8 cb2 9 cg2 10 cbe2
// 11 cW3[128,3] 12 cb3
// 13 rW1[4,96,128] 14 rb1 15 rg1 16 rbe1  17 rW2[4,128,64] 18 rb2 19 rg2 20 rbe2
// 21 rW3[4,64,3] 22 rb3      out[B,3] f32

#define EPS 1e-5f
#define BMAX 4096

__device__ int   g_bound[BMAX + 1];
__device__ float g_pooled[BMAX * 96];

// ---------------- kernel 0: boundaries ----------------
__global__ void bounds_kernel(const int* __restrict__ seg, int N, int B) {
    int i = blockIdx.x * blockDim.x + threadIdx.x;
    if (i >= N) return;
    int cur = seg[i];
    int prev = (i == 0) ? -1 : seg[i - 1];
    for (int b = prev + 1; b <= cur; b++) g_bound[b] = i;
    if (i == N - 1)
        for (int b = cur + 1; b <= B; b++) g_bound[b] = N;
}

// ---------------- kernel 1: pooling, warp per sample ----------------
// Per 4-row chunk (384 floats = 96 float4), lane l + slot j (j=0..2) owns
// flat float4 index i = j*32+l -> row offset i/24, channel 4*(i%24).
__global__ __launch_bounds__(256) void pool_kernel(const float* __restrict__ feat, int B) {
    __shared__ float4 spart[8][4][24];
    const int tid = threadIdx.x, lane = tid & 31, w = tid >> 5;
    const int b = blockIdx.x * 8 + w;
    if (b >= B) return;                       // warp-uniform; no block syncs below

    const int start = g_bound[b], end = g_bound[b + 1];
    const int nrows = end - start;
    const float* base = feat + (size_t)start * 96;

    const int i0 = lane, i1 = lane + 32, i2 = lane + 64;
    const int ro0 = i0 / 24, ro1 = i1 / 24, ro2 = i2 / 24;
    const int co0 = 4 * (i0 % 24), co1 = 4 * (i1 % 24), co2 = 4 * (i2 % 24);
    const float* p0 = base + ro0 * 96 + co0;
    const float* p1 = base + ro1 * 96 + co1;
    const float* p2 = base + ro2 * 96 + co2;

    float4 a0 = make_float4(0.f, 0.f, 0.f, 0.f), a1 = a0, a2 = a0;
    int r0 = 0;
    for (; r0 + 8 <= nrows; r0 += 8) {
        float4 v0 = *(const float4*)(p0 + (size_t)r0 * 96);
        float4 v1 = *(const float4*)(p1 + (size_t)r0 * 96);
        float4 v2 = *(const float4*)(p2 + (size_t)r0 * 96);
        float4 v3 = *(const float4*)(p0 + (size_t)(r0 + 4) * 96);
        float4 v4 = *(const float4*)(p1 + (size_t)(r0 + 4) * 96);
        float4 v5 = *(const float4*)(p2 + (size_t)(r0 + 4) * 96);
        a0.x += v0.x; a0.y += v0.y; a0.z += v0.z; a0.w += v0.w;
        a1.x += v1.x; a1.y += v1.y; a1.z += v1.z; a1.w += v1.w;
        a2.x += v2.x; a2.y += v2.y; a2.z += v2.z; a2.w += v2.w;
        a0.x += v3.x; a0.y += v3.y; a0.z += v3.z; a0.w += v3.w;
        a1.x += v4.x; a1.y += v4.y; a1.z += v4.z; a1.w += v4.w;
        a2.x += v5.x; a2.y += v5.y; a2.z += v5.z; a2.w += v5.w;
    }
    for (; r0 < nrows; r0 += 4) {
        if (r0 + ro0 < nrows) {
            float4 v = *(const float4*)(p0 + (size_t)r0 * 96);
            a0.x += v.x; a0.y += v.y; a0.z += v.z; a0.w += v.w;
        }
        if (r0 + ro1 < nrows) {
            float4 v = *(const float4*)(p1 + (size_t)r0 * 96);
            a1.x += v.x; a1.y += v.y; a1.z += v.z; a1.w += v.w;
        }
        if (r0 + ro2 < nrows) {
            float4 v = *(const float4*)(p2 + (size_t)r0 * 96);
            a2.x += v.x; a2.y += v.y; a2.z += v.z; a2.w += v.w;
        }
    }
    spart[w][ro0][co0 >> 2] = a0;
    spart[w][ro1][co1 >> 2] = a1;
    spart[w][ro2][co2 >> 2] = a2;
    __syncwarp();

    const float inv = 1.f / fmaxf((float)nrows, 1.f);
    const float* sp = (const float*)&spart[w][0][0];
#pragma unroll
    for (int j = 0; j < 3; j++) {
        int c = lane + j * 32;
        float s = sp[c] + sp[96 + c] + sp[192 + c] + sp[288 + c];
        g_pooled[b * 96 + c] = s * inv;
    }
}

// ---------------- kernel 2: batched MLP ----------------
__device__ __forceinline__ float warpSum(float v) {
#pragma unroll
    for (int o = 16; o; o >>= 1) v += __shfl_xor_sync(0xffffffffu, v, o);
    return v;
}

// Dense(CIN->F) + LayerNorm + ReLU over 16 samples.
// Thread owns feature f = tid % F for samples gt*SPG .. gt*SPG+SPG-1.
template <int F, int CIN>
__device__ __forceinline__ void dense_ln_relu(
    const float* in, float* outb,
    const float* __restrict__ W, const float* __restrict__ bias,
    const float* __restrict__ gamma, const float* __restrict__ beta,
    int tid, float* wred, float* smean, float* svar)
{
    constexpr int G = 256 / F;
    constexpr int SPG = 16 / G;
    constexpr int WPG = F / 32;
    const int f = tid % F, gt = tid / F;
    const int lane = tid & 31, w = tid >> 5;
    const float* inb = in + gt * SPG * CIN;

    float x[SPG];
    const float bv = bias[f];
#pragma unroll
    for (int i = 0; i < SPG; i++) x[i] = bv;

#pragma unroll 2
    for (int c = 0; c < CIN; c += 4) {
        float w0 = W[(c + 0) * F + f];
        float w1 = W[(c + 1) * F + f];
        float w2 = W[(c + 2) * F + f];
        float w3 = W[(c + 3) * F + f];
#pragma unroll
        for (int i = 0; i < SPG; i++) {
            float4 v = *(const float4*)(inb + i * CIN + c);
            x[i] = fmaf(v.x, w0, x[i]);
            x[i] = fmaf(v.y, w1, x[i]);
            x[i] = fmaf(v.z, w2, x[i]);
            x[i] = fmaf(v.w, w3, x[i]);
        }
    }

    // mean
#pragma unroll
    for (int i = 0; i < SPG; i++) {
        float r = warpSum(x[i]);
        if (lane == 0) wred[w * SPG + i] = r;
    }
    __syncthreads();
    if (tid < 16) {
        int g = tid / SPG, i = tid % SPG;
        float m = 0.f;
#pragma unroll
        for (int dw = 0; dw < WPG; dw++) m += wred[(g * WPG + dw) * SPG + i];
        smean[tid] = m * (1.0f / F);
    }
    __syncthreads();
    // variance
#pragma unroll
    for (int i = 0; i < SPG; i++) {
        float d = x[i] - smean[gt * SPG + i];
        float r = warpSum(d * d);
        if (lane == 0) wred[w * SPG + i] = r;
    }
    __syncthreads();
    if (tid < 16) {
        int g = tid / SPG, i = tid % SPG;
        float v = 0.f;
#pragma unroll
        for (int dw = 0; dw < WPG; dw++) v += wred[(g * WPG + dw) * SPG + i];
        svar[tid] = v * (1.0f / F);
    }
    __syncthreads();

    const float gm = gamma[f], bt = beta[f];
#pragma unroll
    for (int i = 0; i < SPG; i++) {
        int s = gt * SPG + i;
        float v = (x[i] - smean[s]) * rsqrtf(svar[s] + EPS);
        outb[s * F + f] = fmaxf(fmaf(v, gm, bt), 0.f);
    }
    __syncthreads();
}

__global__ __launch_bounds__(256) void mlp_kernel(
    const int* __restrict__ cls,
    const float* __restrict__ cW1, const float* __restrict__ cb1,
    const float* __restrict__ cg1, const float* __restrict__ cbe1,
    const float* __restrict__ cW2, const float* __restrict__ cb2,
    const float* __restrict__ cg2, const float* __restrict__ cbe2,
    const float* __restrict__ cW3, const float* __restrict__ cb3,
    const float* __restrict__ rW1, const float* __restrict__ rb1,
    const float* __restrict__ rg1, const float* __restrict__ rbe1,
    const float* __restrict__ rW2, const float* __restrict__ rb2,
    const float* __restrict__ rg2, const float* __restrict__ rbe2,
    const float* __restrict__ rW3, const float* __restrict__ rb3,
    float* __restrict__ out, int B)
{
    __shared__ float sp[16 * 96];
    __shared__ float bufA[16 * 256];
    __shared__ float bufB[16 * 128];
    __shared__ float wred[128];
    __shared__ float smean[16], svar[16];
    __shared__ int scls[16];
    __shared__ int smask;

    const int tid = threadIdx.x;
    const int s0 = blockIdx.x * 16;

    for (int idx = tid; idx < 16 * 96; idx += 256)
        sp[idx] = g_pooled[s0 * 96 + idx];
    if (tid < 16) scls[tid] = cls[min(s0 + tid, B - 1)];
    if (tid == 0) smask = 0;
    __syncthreads();
    if (tid < 16) atomicOr(&smask, 1 << scls[tid]);
    __syncthreads();
    const int mask = smask;

    // coarse head
    dense_ln_relu<256, 96>(sp, bufA, cW1, cb1, cg1, cbe1, tid, wred, smean, svar);
    dense_ln_relu<128, 256>(bufA, bufB, cW2, cb2, cg2, cbe2, tid, wred, smean, svar);

    float coarse = 0.f, roff = 0.f;
    const int ss = tid / 3, oo = tid % 3;
    if (tid < 48) {
        coarse = cb3[oo];
#pragma unroll 4
        for (int c = 0; c < 128; c++)
            coarse = fmaf(bufB[ss * 128 + c], cW3[c * 3 + oo], coarse);
    }
    __syncthreads();

    // refinement heads (only classes present in this CTA)
    for (int k = 0; k < 4; k++) {
        if (!((mask >> k) & 1)) continue;
        dense_ln_relu<128, 96>(sp, bufA, rW1 + k * 96 * 128, rb1 + k * 128,
                               rg1 + k * 128, rbe1 + k * 128, tid, wred, smean, svar);
        dense_ln_relu<64, 128>(bufA, bufB, rW2 + k * 128 * 64, rb2 + k * 64,
                               rg2 + k * 64, rbe2 + k * 64, tid, wred, smean, svar);
        if (tid < 48 && scls[ss] == k) {
            float o = rb3[k * 3 + oo];
#pragma unroll 4
            for (int c = 0; c < 64; c++)
                o = fmaf(bufB[ss * 64 + c], rW3[k * 192 + c * 3 + oo], o);
            roff = o;
        }
        __syncthreads();
    }

    if (tid < 48 && (s0 + ss) < B)
        out[(s0 + ss) * 3 + oo] = coarse + roff;
}

// ---------------- launch ----------------
extern "C" void kernel_launch(void* const* d_in, const int* in_sizes, int n_in,
                              void* d_out, int out_size) {
    const float* feat = (const float*)d_in[0];
    const int*   seg  = (const int*)d_in[1];
    const int*   cls  = (const int*)d_in[2];
    const int N = in_sizes[1];
    const int B = in_sizes[2];

    bounds_kernel<<<(N + 255) / 256, 256>>>(seg, N, B);
    pool_kernel<<<(B + 7) / 8, 256>>>(feat, B);
    mlp_kernel<<<(B + 15) / 16, 256>>>(
        cls,
        (const float*)d_in[3],  (const float*)d_in[4],  (const float*)d_in[5],  (const float*)d_in[6],
        (const float*)d_in[7],  (const float*)d_in[8],  (const float*)d_in[9],  (const float*)d_in[10],
        (const float*)d_in[11], (const float*)d_in[12],
        (const float*)d_in[13], (const float*)d_in[14], (const float*)d_in[15], (const float*)d_in[16],
        (const float*)d_in[17], (const float*)d_in[18], (const float*)d_in[19], (const float*)d_in[20],
        (const float*)d_in[21], (const float*)d_in[22],
        (float*)d_out, B);
}

// round 3
// speedup vs baseline: 1.5520x; 1.2342x over previous
#include <cuda_runtime.h>

// VoxelBracketPredictor_v2 — 4-kernel pipeline:
//  k0 bounds: segment boundaries (int4 scan of sorted segment_ids)
//  k1 group:  stable class-sort of sample indices + CTA descriptors (1 CTA)
//  k2 pool:   mean-pool, warp per sample, 12 LDG.128 in flight
//  k3 mlp:    16 same-class samples per CTA -> coarse head + exactly ONE refinement head

#define EPS 1e-5f
#define BMAX 4096
#define MAXCTA 264

__device__ int   g_bound[BMAX + 1];
__device__ float g_pooled[BMAX * 96];
__device__ int   g_order[BMAX];
__device__ int   g_ctaK[MAXCTA];
__device__ int   g_ctaBase[MAXCTA];
__device__ int   g_ctaCnt[MAXCTA];

// ---------------- kernel 0: boundaries ----------------
__global__ void bounds_kernel(const int* __restrict__ seg, int N, int B) {
    int t = blockIdx.x * blockDim.x + threadIdx.x;
    int i = t * 4;
    if (i >= N) return;
    int vals[4];
    if (i + 4 <= N) {
        int4 v = *(const int4*)(seg + i);
        vals[0] = v.x; vals[1] = v.y; vals[2] = v.z; vals[3] = v.w;
    } else {
        for (int j = 0; j < 4; j++) vals[j] = (i + j < N) ? seg[i + j] : vals[j > 0 ? j - 1 : 0];
    }
    int prev = (i == 0) ? -1 : seg[i - 1];
    int lim = min(4, N - i);
    for (int j = 0; j < lim; j++) {
        int cur = vals[j];
        for (int b = prev + 1; b <= cur; b++) g_bound[b] = i + j;
        prev = cur;
    }
    if (i + 4 >= N)
        for (int b = prev + 1; b <= B; b++) g_bound[b] = N;
}

// ---------------- kernel 1: class grouping (1 CTA, 256 threads) ----------------
__global__ __launch_bounds__(256) void group_kernel(const int* __restrict__ cls, int B) {
    __shared__ short scls[BMAX];
    __shared__ int scnt[4][256];
    __shared__ int sbase[4];
    const int tid = threadIdx.x;

    for (int i = tid; i < B; i += 256) scls[i] = (short)cls[i];
    __syncthreads();

    const int chunk = (B + 255) / 256;
    const int lo = tid * chunk, hi = min(lo + chunk, B);
    int c[4] = {0, 0, 0, 0};
    for (int i = lo; i < hi; i++) c[scls[i]]++;
#pragma unroll
    for (int k = 0; k < 4; k++) scnt[k][tid] = c[k];
    __syncthreads();

    int pre[4] = {0, 0, 0, 0};
    for (int j = 0; j < tid; j++)
#pragma unroll
        for (int k = 0; k < 4; k++) pre[k] += scnt[k][j];

    if (tid == 255) {
        int tot[4];
#pragma unroll
        for (int k = 0; k < 4; k++) tot[k] = pre[k] + c[k];
        int b0 = 0;
#pragma unroll
        for (int k = 0; k < 4; k++) { sbase[k] = b0; b0 += tot[k]; }
        int ci = 0;
        for (int k = 0; k < 4; k++) {
            int base = sbase[k];
            for (int off = 0; off < tot[k]; off += 16) {
                g_ctaK[ci] = k;
                g_ctaBase[ci] = base + off;
                g_ctaCnt[ci] = min(16, tot[k] - off);
                ci++;
            }
        }
        for (; ci < MAXCTA; ci++) g_ctaK[ci] = -1;
    }
    __syncthreads();

    int pos[4];
#pragma unroll
    for (int k = 0; k < 4; k++) pos[k] = sbase[k] + pre[k];
    for (int i = lo; i < hi; i++) { int k = scls[i]; g_order[pos[k]++] = i; }
}

// ---------------- kernel 2: pooling, warp per sample, 12 loads in flight ----------------
__global__ __launch_bounds__(256) void pool_kernel(const float* __restrict__ feat, int B) {
    __shared__ float4 spart[8][4][24];
    const int tid = threadIdx.x, lane = tid & 31, w = tid >> 5;
    const int b = blockIdx.x * 8 + w;
    if (b >= B) return;

    const int start = g_bound[b], end = g_bound[b + 1];
    const int nrows = end - start;
    const float* base = feat + (size_t)start * 96;

    const int i0 = lane, i1 = lane + 32, i2 = lane + 64;
    const int ro0 = i0 / 24, ro1 = i1 / 24, ro2 = i2 / 24;
    const int co0 = 4 * (i0 % 24), co1 = 4 * (i1 % 24), co2 = 4 * (i2 % 24);
    const float* p0 = base + ro0 * 96 + co0;
    const float* p1 = base + ro1 * 96 + co1;
    const float* p2 = base + ro2 * 96 + co2;

    float4 a0 = make_float4(0.f, 0.f, 0.f, 0.f), a1 = a0, a2 = a0;
    int r0 = 0;
    // 16 rows per iter -> 12 independent LDG.128 per lane
    for (; r0 + 16 <= nrows; r0 += 16) {
        float4 v0 = *(const float4*)(p0 + (size_t)(r0 +  0) * 96);
        float4 v1 = *(const float4*)(p1 + (size_t)(r0 +  0) * 96);
        float4 v2 = *(const float4*)(p2 + (size_t)(r0 +  0) * 96);
        float4 v3 = *(const float4*)(p0 + (size_t)(r0 +  4) * 96);
        float4 v4 = *(const float4*)(p1 + (size_t)(r0 +  4) * 96);
        float4 v5 = *(const float4*)(p2 + (size_t)(r0 +  4) * 96);
        float4 v6 = *(const float4*)(p0 + (size_t)(r0 +  8) * 96);
        float4 v7 = *(const float4*)(p1 + (size_t)(r0 +  8) * 96);
        float4 v8 = *(const float4*)(p2 + (size_t)(r0 +  8) * 96);
        float4 v9 = *(const float4*)(p0 + (size_t)(r0 + 12) * 96);
        float4 va = *(const float4*)(p1 + (size_t)(r0 + 12) * 96);
        float4 vb = *(const float4*)(p2 + (size_t)(r0 + 12) * 96);
        a0.x += v0.x; a0.y += v0.y; a0.z += v0.z; a0.w += v0.w;
        a1.x += v1.x; a1.y += v1.y; a1.z += v1.z; a1.w += v1.w;
        a2.x += v2.x; a2.y += v2.y; a2.z += v2.z; a2.w += v2.w;
        a0.x += v3.x; a0.y += v3.y; a0.z += v3.z; a0.w += v3.w;
        a1.x += v4.x; a1.y += v4.y; a1.z += v4.z; a1.w += v4.w;
        a2.x += v5.x; a2.y += v5.y; a2.z += v5.z; a2.w += v5.w;
        a0.x += v6.x; a0.y += v6.y; a0.z += v6.z; a0.w += v6.w;
        a1.x += v7.x; a1.y += v7.y; a1.z += v7.z; a1.w += v7.w;
        a2.x += v8.x; a2.y += v8.y; a2.z += v8.z; a2.w += v8.w;
        a0.x += v9.x; a0.y += v9.y; a0.z += v9.z; a0.w += v9.w;
        a1.x += va.x; a1.y += va.y; a1.z += va.z; a1.w += va.w;
        a2.x += vb.x; a2.y += vb.y; a2.z += vb.z; a2.w += vb.w;
    }
    for (; r0 + 8 <= nrows; r0 += 8) {
        float4 v0 = *(const float4*)(p0 + (size_t)r0 * 96);
        float4 v1 = *(const float4*)(p1 + (size_t)r0 * 96);
        float4 v2 = *(const float4*)(p2 + (size_t)r0 * 96);
        float4 v3 = *(const float4*)(p0 + (size_t)(r0 + 4) * 96);
        float4 v4 = *(const float4*)(p1 + (size_t)(r0 + 4) * 96);
        float4 v5 = *(const float4*)(p2 + (size_t)(r0 + 4) * 96);
        a0.x += v0.x; a0.y += v0.y; a0.z += v0.z; a0.w += v0.w;
        a1.x += v1.x; a1.y += v1.y; a1.z += v1.z; a1.w += v1.w;
        a2.x += v2.x; a2.y += v2.y; a2.z += v2.z; a2.w += v2.w;
        a0.x += v3.x; a0.y += v3.y; a0.z += v3.z; a0.w += v3.w;
        a1.x += v4.x; a1.y += v4.y; a1.z += v4.z; a1.w += v4.w;
        a2.x += v5.x; a2.y += v5.y; a2.z += v5.z; a2.w += v5.w;
    }
    for (; r0 < nrows; r0 += 4) {
        if (r0 + ro0 < nrows) {
            float4 v = *(const float4*)(p0 + (size_t)r0 * 96);
            a0.x += v.x; a0.y += v.y; a0.z += v.z; a0.w += v.w;
        }
        if (r0 + ro1 < nrows) {
            float4 v = *(const float4*)(p1 + (size_t)r0 * 96);
            a1.x += v.x; a1.y += v.y; a1.z += v.z; a1.w += v.w;
        }
        if (r0 + ro2 < nrows) {
            float4 v = *(const float4*)(p2 + (size_t)r0 * 96);
            a2.x += v.x; a2.y += v.y; a2.z += v.z; a2.w += v.w;
        }
    }
    spart[w][ro0][co0 >> 2] = a0;
    spart[w][ro1][co1 >> 2] = a1;
    spart[w][ro2][co2 >> 2] = a2;
    __syncwarp();

    const float inv = 1.f / fmaxf((float)nrows, 1.f);
    const float* sp = (const float*)&spart[w][0][0];
#pragma unroll
    for (int j = 0; j < 3; j++) {
        int c = lane + j * 32;
        float s = sp[c] + sp[96 + c] + sp[192 + c] + sp[288 + c];
        g_pooled[b * 96 + c] = s * inv;
    }
}

// ---------------- kernel 3: batched MLP, one class per CTA ----------------
__device__ __forceinline__ float warpSum(float v) {
#pragma unroll
    for (int o = 16; o; o >>= 1) v += __shfl_xor_sync(0xffffffffu, v, o);
    return v;
}

template <int F, int CIN>
__device__ __forceinline__ void dense_ln_relu(
    const float* in, float* outb,
    const float* __restrict__ W, const float* __restrict__ bias,
    const float* __restrict__ gamma, const float* __restrict__ beta,
    int tid, float* wred, float* smean, float* svar)
{
    constexpr int G = 256 / F;
    constexpr int SPG = 16 / G;
    constexpr int WPG = F / 32;
    const int f = tid % F, gt = tid / F;
    const int lane = tid & 31, w = tid >> 5;
    const float* inb = in + gt * SPG * CIN;

    float x[SPG];
    const float bv = bias[f];
#pragma unroll
    for (int i = 0; i < SPG; i++) x[i] = bv;

#pragma unroll 2
    for (int c = 0; c < CIN; c += 4) {
        float w0 = W[(c + 0) * F + f];
        float w1 = W[(c + 1) * F + f];
        float w2 = W[(c + 2) * F + f];
        float w3 = W[(c + 3) * F + f];
#pragma unroll
        for (int i = 0; i < SPG; i++) {
            float4 v = *(const float4*)(inb + i * CIN + c);
            x[i] = fmaf(v.x, w0, x[i]);
            x[i] = fmaf(v.y, w1, x[i]);
            x[i] = fmaf(v.z, w2, x[i]);
            x[i] = fmaf(v.w, w3, x[i]);
        }
    }

#pragma unroll
    for (int i = 0; i < SPG; i++) {
        float r = warpSum(x[i]);
        if (lane == 0) wred[w * SPG + i] = r;
    }
    __syncthreads();
    if (tid < 16) {
        int g = tid / SPG, i = tid % SPG;
        float m = 0.f;
#pragma unroll
        for (int dw = 0; dw < WPG; dw++) m += wred[(g * WPG + dw) * SPG + i];
        smean[tid] = m * (1.0f / F);
    }
    __syncthreads();
#pragma unroll
    for (int i = 0; i < SPG; i++) {
        float d = x[i] - smean[gt * SPG + i];
        float r = warpSum(d * d);
        if (lane == 0) wred[w * SPG + i] = r;
    }
    __syncthreads();
    if (tid < 16) {
        int g = tid / SPG, i = tid % SPG;
        float v = 0.f;
#pragma unroll
        for (int dw = 0; dw < WPG; dw++) v += wred[(g * WPG + dw) * SPG + i];
        svar[tid] = v * (1.0f / F);
    }
    __syncthreads();

    const float gm = gamma[f], bt = beta[f];
#pragma unroll
    for (int i = 0; i < SPG; i++) {
        int s = gt * SPG + i;
        float v = (x[i] - smean[s]) * rsqrtf(svar[s] + EPS);
        outb[s * F + f] = fmaxf(fmaf(v, gm, bt), 0.f);
    }
    __syncthreads();
}

__global__ __launch_bounds__(256) void mlp_kernel(
    const float* __restrict__ cW1, const float* __restrict__ cb1,
    const float* __restrict__ cg1, const float* __restrict__ cbe1,
    const float* __restrict__ cW2, const float* __restrict__ cb2,
    const float* __restrict__ cg2, const float* __restrict__ cbe2,
    const float* __restrict__ cW3, const float* __restrict__ cb3,
    const float* __restrict__ rW1, const float* __restrict__ rb1,
    const float* __restrict__ rg1, const float* __restrict__ rbe1,
    const float* __restrict__ rW2, const float* __restrict__ rb2,
    const float* __restrict__ rg2, const float* __restrict__ rbe2,
    const float* __restrict__ rW3, const float* __restrict__ rb3,
    float* __restrict__ out)
{
    const int k = g_ctaK[blockIdx.x];
    if (k < 0) return;
    const int base = g_ctaBase[blockIdx.x];
    const int cnt  = g_ctaCnt[blockIdx.x];

    __shared__ int sidx[16];
    __shared__ float sp[16 * 96];
    __shared__ float bufA[16 * 256];
    __shared__ float bufB[16 * 128];
    __shared__ float wred[128];
    __shared__ float smean[16], svar[16];

    const int tid = threadIdx.x;
    if (tid < 16) sidx[tid] = g_order[base + min(tid, cnt - 1)];
    __syncthreads();

    for (int idx = tid; idx < 16 * 96; idx += 256) {
        int s = idx / 96, c = idx - 96 * s;
        sp[idx] = g_pooled[sidx[s] * 96 + c];
    }
    __syncthreads();

    // coarse head
    dense_ln_relu<256, 96>(sp, bufA, cW1, cb1, cg1, cbe1, tid, wred, smean, svar);
    dense_ln_relu<128, 256>(bufA, bufB, cW2, cb2, cg2, cbe2, tid, wred, smean, svar);

    float coarse = 0.f;
    const int ss = tid / 3, oo = tid % 3;
    if (tid < 48) {
        coarse = cb3[oo];
#pragma unroll 4
        for (int c = 0; c < 128; c++)
            coarse = fmaf(bufB[ss * 128 + c], cW3[c * 3 + oo], coarse);
    }
    __syncthreads();

    // refinement: exactly one head (class k) for all samples in this CTA
    dense_ln_relu<128, 96>(sp, bufA, rW1 + k * 96 * 128, rb1 + k * 128,
                           rg1 + k * 128, rbe1 + k * 128, tid, wred, smean, svar);
    dense_ln_relu<64, 128>(bufA, bufB, rW2 + k * 128 * 64, rb2 + k * 64,
                           rg2 + k * 64, rbe2 + k * 64, tid, wred, smean, svar);

    if (tid < 48 && ss < cnt) {
        float o = rb3[k * 3 + oo];
#pragma unroll 4
        for (int c = 0; c < 64; c++)
            o = fmaf(bufB[ss * 64 + c], rW3[k * 192 + c * 3 + oo], o);
        out[sidx[ss] * 3 + oo] = coarse + o;
    }
}

// ---------------- launch ----------------
extern "C" void kernel_launch(void* const* d_in, const int* in_sizes, int n_in,
                              void* d_out, int out_size) {
    const float* feat = (const float*)d_in[0];
    const int*   seg  = (const int*)d_in[1];
    const int*   cls  = (const int*)d_in[2];
    const int N = in_sizes[1];
    const int B = in_sizes[2];

    bounds_kernel<<<(N / 4 + 255) / 256, 256>>>(seg, N, B);
    group_kernel<<<1, 256>>>(cls, B);
    pool_kernel<<<(B + 7) / 8, 256>>>(feat, B);
    mlp_kernel<<<MAXCTA, 256>>>(
        (const float*)d_in[3],  (const float*)d_in[4],  (const float*)d_in[5],  (const float*)d_in[6],
        (const float*)d_in[7],  (const float*)d_in[8],  (const float*)d_in[9],  (const float*)d_in[10],
        (const float*)d_in[11], (const float*)d_in[12],
        (const float*)d_in[13], (const float*)d_in[14], (const float*)d_in[15], (const float*)d_in[16],
        (const float*)d_in[17], (const float*)d_in[18], (const float*)d_in[19], (const float*)d_in[20],
        (const float*)d_in[21], (const float*)d_in[22],
        (float*)d_out);
}